// round 1
// baseline (speedup 1.0000x reference)
#include <cuda_runtime.h>
#include <math.h>

#define NN    100000
#define EE    3200000
#define IN_F  256
#define OUT_F 128

// Scratch (allocation-free rule: __device__ globals)
__device__ float g_h[(size_t)NN * OUT_F];   // 51.2 MB
__device__ float g_e[EE];                   // 12.8 MB (e_exp per edge)
__device__ float g_sl[NN];
__device__ float g_sr[NN];
__device__ float g_denom[NN];

// ---------------------------------------------------------------------------
// Zero out + denom (d_out is poisoned; empty segments must be exactly 0)
// ---------------------------------------------------------------------------
__global__ void init_kernel(float* __restrict__ out) {
    int i = blockIdx.x * blockDim.x + threadIdx.x;
    if (i < NN * OUT_F) out[i] = 0.0f;
    if (i < NN) g_denom[i] = 0.0f;
}

// ---------------------------------------------------------------------------
// h = x @ W   (100000x256 @ 256x128), fp32 SIMT tiled GEMM
// Block: 256 threads, tile 64 rows x 128 cols. Each thread: 8 rows x 4 cols.
// ---------------------------------------------------------------------------
__global__ __launch_bounds__(256) void gemm_kernel(const float* __restrict__ x,
                                                   const float* __restrict__ w) {
    __shared__ float xs[64][32];
    __shared__ float ws[32][128];
    const int t    = threadIdx.x;
    const int lane = t & 31;   // column quad: cols lane*4 .. lane*4+3
    const int wy   = t >> 5;   // row group: rows wy*8 .. wy*8+7
    const int row0 = blockIdx.x * 64;

    float4 acc[8];
#pragma unroll
    for (int r = 0; r < 8; r++) acc[r] = make_float4(0.f, 0.f, 0.f, 0.f);

    for (int k0 = 0; k0 < IN_F; k0 += 32) {
        // x tile: 64x32 floats = 512 float4, 2 per thread
#pragma unroll
        for (int l = 0; l < 2; l++) {
            int idx4 = t + l * 256;
            int row  = idx4 >> 3, kq = idx4 & 7;
            float4 v = make_float4(0.f, 0.f, 0.f, 0.f);
            if (row0 + row < NN)
                v = *(const float4*)(x + (size_t)(row0 + row) * IN_F + k0 + kq * 4);
            *((float4*)&xs[row][kq * 4]) = v;
        }
        // w tile: 32x128 floats = 1024 float4, 4 per thread
#pragma unroll
        for (int l = 0; l < 4; l++) {
            int idx4 = t + l * 256;
            int kk   = idx4 >> 5, cq = idx4 & 31;
            *((float4*)&ws[kk][cq * 4]) =
                *(const float4*)(w + (size_t)(k0 + kk) * OUT_F + cq * 4);
        }
        __syncthreads();
#pragma unroll
        for (int kk = 0; kk < 32; kk++) {
            float4 wv = *(float4*)&ws[kk][lane * 4];
#pragma unroll
            for (int r = 0; r < 8; r++) {
                float xv = xs[wy * 8 + r][kk];   // warp-uniform broadcast
                acc[r].x += xv * wv.x;
                acc[r].y += xv * wv.y;
                acc[r].z += xv * wv.z;
                acc[r].w += xv * wv.w;
            }
        }
        __syncthreads();
    }
#pragma unroll
    for (int r = 0; r < 8; r++) {
        int row = row0 + wy * 8 + r;
        if (row < NN)
            *((float4*)(g_h + (size_t)row * OUT_F + lane * 4)) = acc[r];
    }
}

// ---------------------------------------------------------------------------
// s_l[i] = h[i,:] . a[0:128],  s_r[i] = h[i,:] . a[128:256]; one warp per node
// ---------------------------------------------------------------------------
__global__ void score_kernel(const float* __restrict__ a) {
    int gw   = (blockIdx.x * blockDim.x + threadIdx.x) >> 5;
    int lane = threadIdx.x & 31;
    if (gw >= NN) return;
    float4 hv = *(const float4*)(g_h + (size_t)gw * OUT_F + lane * 4);
    float4 al = *(const float4*)(a + lane * 4);
    float4 ar = *(const float4*)(a + OUT_F + lane * 4);
    float sl = hv.x * al.x + hv.y * al.y + hv.z * al.z + hv.w * al.w;
    float sr = hv.x * ar.x + hv.y * ar.y + hv.z * ar.z + hv.w * ar.w;
#pragma unroll
    for (int o = 16; o > 0; o >>= 1) {
        sl += __shfl_xor_sync(0xffffffffu, sl, o);
        sr += __shfl_xor_sync(0xffffffffu, sr, o);
    }
    if (lane == 0) { g_sl[gw] = sl; g_sr[gw] = sr; }
}

// ---------------------------------------------------------------------------
// Pass 1: per edge, e_exp = exp(leakyrelu(s_l[src]+s_r[dst])); denom[src] += e_exp
// (segment-max skipped: e is bounded ~|17| so exp() is safe in fp32, and
//  exp(e)/sum(exp(e)) is identical to the max-shifted computation)
// ---------------------------------------------------------------------------
__global__ void edge1_kernel(const int* __restrict__ ei) {
    int e = blockIdx.x * blockDim.x + threadIdx.x;
    if (e >= EE) return;
    int s = ei[e], d = ei[EE + e];
    float v = g_sl[s] + g_sr[d];
    v = (v >= 0.f) ? v : 0.2f * v;
    float ex = __expf(v);
    g_e[e] = ex;
    atomicAdd(&g_denom[s], ex);
}

// ---------------------------------------------------------------------------
// Pass 2: out[src] += (e_exp/denom[src]) * h[dst]; one warp per edge,
// float4 per lane, red.global.add.v4.f32 scatter (no return, 4x fewer ops)
// ---------------------------------------------------------------------------
__global__ void edge2_kernel(const int* __restrict__ ei, float* __restrict__ out) {
    unsigned gt = blockIdx.x * blockDim.x + threadIdx.x;
    int e    = (int)(gt >> 5);
    int lane = threadIdx.x & 31;
    if (e >= EE) return;
    int s = ei[e], d = ei[EE + e];
    float alpha = g_e[e] / (g_denom[s] + 1e-16f);
    float4 hv = *(const float4*)(g_h + (size_t)d * OUT_F + lane * 4);
    float* p = out + (size_t)s * OUT_F + lane * 4;
    asm volatile("red.global.add.v4.f32 [%0], {%1,%2,%3,%4};"
                 :: "l"(p),
                    "f"(alpha * hv.x), "f"(alpha * hv.y),
                    "f"(alpha * hv.z), "f"(alpha * hv.w)
                 : "memory");
}

// ---------------------------------------------------------------------------
extern "C" void kernel_launch(void* const* d_in, const int* in_sizes, int n_in,
                              void* d_out, int out_size) {
    const float* x  = (const float*)d_in[0];
    const int*   ei = (const int*)d_in[1];
    const float* w  = (const float*)d_in[2];
    const float* a  = (const float*)d_in[3];
    float* out = (float*)d_out;

    init_kernel<<<(NN * OUT_F + 255) / 256, 256>>>(out);
    gemm_kernel<<<(NN + 63) / 64, 256>>>(x, w);
    score_kernel<<<(NN * 32 + 255) / 256, 256>>>(a);
    edge1_kernel<<<(EE + 255) / 256, 256>>>(ei);
    edge2_kernel<<<(unsigned)(((size_t)EE * 32 + 255) / 256), 256>>>(ei, out);
}

// round 2
// speedup vs baseline: 1.3556x; 1.3556x over previous
#include <cuda_runtime.h>
#include <math.h>

#define NN    100000
#define EE    3200000
#define IN_F  256
#define OUT_F 128

// Scratch (allocation-free rule: __device__ globals)
__device__ float g_h[(size_t)NN * OUT_F];   // 51.2 MB
__device__ float g_sl[NN];
__device__ float g_sr[NN];
__device__ int   g_cnt[NN];                 // per-src degree
__device__ int   g_off[NN + 1];             // CSR offsets
__device__ int   g_fill[NN];                // scatter cursors
__device__ int   g_cdst[EE];                // dst ids grouped by src

// ---------------------------------------------------------------------------
__global__ void zero_cnt_kernel() {
    int i = blockIdx.x * blockDim.x + threadIdx.x;
    if (i < NN) g_cnt[i] = 0;
}

// histogram of src
__global__ void hist_kernel(const int* __restrict__ ei) {
    int e = blockIdx.x * blockDim.x + threadIdx.x;
    if (e < EE) atomicAdd(&g_cnt[ei[e]], 1);
}

// exclusive scan of g_cnt -> g_off, g_fill (single 1024-thread block)
__global__ __launch_bounds__(1024) void scan_kernel() {
    __shared__ int sm[1024];
    const int CHUNK = (NN + 1023) / 1024;   // 98
    int t  = threadIdx.x;
    int lo = t * CHUNK;
    int hi = min(lo + CHUNK, NN);
    int s = 0;
    for (int i = lo; i < hi; i++) s += g_cnt[i];
    sm[t] = s;
    __syncthreads();
    for (int o = 1; o < 1024; o <<= 1) {
        int v = (t >= o) ? sm[t - o] : 0;
        __syncthreads();
        sm[t] += v;
        __syncthreads();
    }
    int run = sm[t] - s;  // exclusive prefix
    for (int i = lo; i < hi; i++) {
        g_off[i]  = run;
        g_fill[i] = run;
        run += g_cnt[i];
    }
    if (t == 1023) g_off[NN] = sm[1023];
}

// scatter dst ids into CSR order
__global__ void scatter_kernel(const int* __restrict__ ei) {
    int e = blockIdx.x * blockDim.x + threadIdx.x;
    if (e >= EE) return;
    int s = ei[e], d = ei[EE + e];
    int pos = atomicAdd(&g_fill[s], 1);
    g_cdst[pos] = d;
}

// ---------------------------------------------------------------------------
// h = x @ W   (100000x256 @ 256x128), fp32 SIMT tiled GEMM
// ---------------------------------------------------------------------------
__global__ __launch_bounds__(256) void gemm_kernel(const float* __restrict__ x,
                                                   const float* __restrict__ w) {
    __shared__ float xs[64][32];
    __shared__ float ws[32][128];
    const int t    = threadIdx.x;
    const int lane = t & 31;
    const int wy   = t >> 5;
    const int row0 = blockIdx.x * 64;

    float4 acc[8];
#pragma unroll
    for (int r = 0; r < 8; r++) acc[r] = make_float4(0.f, 0.f, 0.f, 0.f);

    for (int k0 = 0; k0 < IN_F; k0 += 32) {
#pragma unroll
        for (int l = 0; l < 2; l++) {
            int idx4 = t + l * 256;
            int row  = idx4 >> 3, kq = idx4 & 7;
            float4 v = make_float4(0.f, 0.f, 0.f, 0.f);
            if (row0 + row < NN)
                v = *(const float4*)(x + (size_t)(row0 + row) * IN_F + k0 + kq * 4);
            *((float4*)&xs[row][kq * 4]) = v;
        }
#pragma unroll
        for (int l = 0; l < 4; l++) {
            int idx4 = t + l * 256;
            int kk   = idx4 >> 5, cq = idx4 & 31;
            *((float4*)&ws[kk][cq * 4]) =
                *(const float4*)(w + (size_t)(k0 + kk) * OUT_F + cq * 4);
        }
        __syncthreads();
#pragma unroll
        for (int kk = 0; kk < 32; kk++) {
            float4 wv = *(float4*)&ws[kk][lane * 4];
#pragma unroll
            for (int r = 0; r < 8; r++) {
                float xv = xs[wy * 8 + r][kk];
                acc[r].x += xv * wv.x;
                acc[r].y += xv * wv.y;
                acc[r].z += xv * wv.z;
                acc[r].w += xv * wv.w;
            }
        }
        __syncthreads();
    }
#pragma unroll
    for (int r = 0; r < 8; r++) {
        int row = row0 + wy * 8 + r;
        if (row < NN)
            *((float4*)(g_h + (size_t)row * OUT_F + lane * 4)) = acc[r];
    }
}

// ---------------------------------------------------------------------------
// s_l[i] = h[i,:] . a[0:128],  s_r[i] = h[i,:] . a[128:256]; one warp per node
// ---------------------------------------------------------------------------
__global__ void score_kernel(const float* __restrict__ a) {
    int gw   = (blockIdx.x * blockDim.x + threadIdx.x) >> 5;
    int lane = threadIdx.x & 31;
    if (gw >= NN) return;
    float4 hv = *(const float4*)(g_h + (size_t)gw * OUT_F + lane * 4);
    float4 al = *(const float4*)(a + lane * 4);
    float4 ar = *(const float4*)(a + OUT_F + lane * 4);
    float sl = hv.x * al.x + hv.y * al.y + hv.z * al.z + hv.w * al.w;
    float sr = hv.x * ar.x + hv.y * ar.y + hv.z * ar.z + hv.w * ar.w;
#pragma unroll
    for (int o = 16; o > 0; o >>= 1) {
        sl += __shfl_xor_sync(0xffffffffu, sl, o);
        sr += __shfl_xor_sync(0xffffffffu, sr, o);
    }
    if (lane == 0) { g_sl[gw] = sl; g_sr[gw] = sr; }
}

// ---------------------------------------------------------------------------
// Node-centric aggregation: one warp per node. Single pass:
//   out[u] = (sum_e w_e * h[dst_e]) / (sum_e w_e + eps)
// w_e = exp(leakyrelu(sl[u] + sr[dst_e])) computed lane-parallel per 32-edge
// chunk, then broadcast via shfl while all 32 lanes gather h[dst] (float4 each,
// 512B coalesced). No atomics anywhere; every output row written exactly once.
// ---------------------------------------------------------------------------
__global__ __launch_bounds__(256) void agg_kernel(float* __restrict__ out) {
    int u    = (blockIdx.x * blockDim.x + threadIdx.x) >> 5;
    int lane = threadIdx.x & 31;
    if (u >= NN) return;
    int beg = g_off[u];
    int end = g_off[u + 1];
    float slu = g_sl[u];

    float4 acc = make_float4(0.f, 0.f, 0.f, 0.f);
    float  wsum = 0.f;

    for (int c = beg; c < end; c += 32) {
        int j  = c + lane;
        int dj = 0;
        float wl = 0.f;
        if (j < end) {
            dj = g_cdst[j];
            float v = slu + g_sr[dj];
            v  = (v >= 0.f) ? v : 0.2f * v;
            wl = __expf(v);
            wsum += wl;
        }
        int m = min(32, end - c);
        for (int k = 0; k < m; k++) {
            int   d = __shfl_sync(0xffffffffu, dj, k);
            float w = __shfl_sync(0xffffffffu, wl, k);
            float4 hv = *(const float4*)(g_h + (size_t)d * OUT_F + lane * 4);
            acc.x += w * hv.x;
            acc.y += w * hv.y;
            acc.z += w * hv.z;
            acc.w += w * hv.w;
        }
    }
#pragma unroll
    for (int o = 16; o > 0; o >>= 1)
        wsum += __shfl_xor_sync(0xffffffffu, wsum, o);
    float inv = 1.0f / (wsum + 1e-16f);
    float4 r = make_float4(acc.x * inv, acc.y * inv, acc.z * inv, acc.w * inv);
    *((float4*)(out + (size_t)u * OUT_F + lane * 4)) = r;
}

// ---------------------------------------------------------------------------
extern "C" void kernel_launch(void* const* d_in, const int* in_sizes, int n_in,
                              void* d_out, int out_size) {
    const float* x  = (const float*)d_in[0];
    const int*   ei = (const int*)d_in[1];
    const float* w  = (const float*)d_in[2];
    const float* a  = (const float*)d_in[3];
    float* out = (float*)d_out;

    // CSR build
    zero_cnt_kernel<<<(NN + 255) / 256, 256>>>();
    hist_kernel<<<(EE + 255) / 256, 256>>>(ei);
    scan_kernel<<<1, 1024>>>();
    scatter_kernel<<<(EE + 255) / 256, 256>>>(ei);

    // Dense pipeline
    gemm_kernel<<<(NN + 63) / 64, 256>>>(x, w);
    score_kernel<<<(NN * 32 + 255) / 256, 256>>>(a);

    // Fused attention + aggregation (no atomics, writes all of out)
    agg_kernel<<<(NN * 32 + 255) / 256, 256>>>(out);
}

// round 5
// speedup vs baseline: 1.5897x; 1.1727x over previous
#include <cuda_runtime.h>
#include <cuda_bf16.h>
#include <math.h>
#include <cstdint>

#define NN    100000
#define EE    3200000
#define IN_F  256
#define OUT_F 128

// Scratch (allocation-free rule: __device__ globals)
__device__ float g_h[(size_t)NN * OUT_F];          // 51.2 MB
__device__ float g_sl[NN];
__device__ float g_sr[NN];
__device__ int   g_cnt[NN];
__device__ int   g_off[NN + 1];
__device__ int   g_fill[NN];
__device__ int   g_cdst[EE];
__device__ __nv_bfloat16 g_wt_hi[OUT_F * IN_F];    // W^T hi  [n][k]
__device__ __nv_bfloat16 g_wt_lo[OUT_F * IN_F];    // W^T lo  [n][k]

// ---------------------------------------------------------------------------
// CSR build
// ---------------------------------------------------------------------------
__global__ void zero_cnt_kernel() {
    int i = blockIdx.x * blockDim.x + threadIdx.x;
    if (i < NN) g_cnt[i] = 0;
}
__global__ void hist_kernel(const int* __restrict__ ei) {
    int e = blockIdx.x * blockDim.x + threadIdx.x;
    if (e < EE) atomicAdd(&g_cnt[ei[e]], 1);
}
__global__ __launch_bounds__(1024) void scan_kernel() {
    __shared__ int sm[1024];
    const int CHUNK = (NN + 1023) / 1024;
    int t = threadIdx.x;
    int lo = t * CHUNK, hi = min(lo + CHUNK, NN);
    int s = 0;
    for (int i = lo; i < hi; i++) s += g_cnt[i];
    sm[t] = s;
    __syncthreads();
    for (int o = 1; o < 1024; o <<= 1) {
        int v = (t >= o) ? sm[t - o] : 0;
        __syncthreads();
        sm[t] += v;
        __syncthreads();
    }
    int run = sm[t] - s;
    for (int i = lo; i < hi; i++) {
        g_off[i] = run;
        g_fill[i] = run;
        run += g_cnt[i];
    }
    if (t == 1023) g_off[NN] = sm[1023];
}
__global__ void scatter_kernel(const int* __restrict__ ei) {
    int e = blockIdx.x * blockDim.x + threadIdx.x;
    if (e >= EE) return;
    int s = ei[e], d = ei[EE + e];
    int pos = atomicAdd(&g_fill[s], 1);
    g_cdst[pos] = d;
}

// ---------------------------------------------------------------------------
// W prep: transpose + bf16 hi/lo split. Wt[n][k] = W[k][n]
// ---------------------------------------------------------------------------
__global__ void wprep_kernel(const float* __restrict__ w) {
    int i = blockIdx.x * blockDim.x + threadIdx.x;   // i = n*IN_F + k
    if (i >= OUT_F * IN_F) return;
    int n = i / IN_F, k = i % IN_F;
    float v = w[(size_t)k * OUT_F + n];
    __nv_bfloat16 h = __float2bfloat16(v);
    g_wt_hi[i] = h;
    g_wt_lo[i] = __float2bfloat16(v - __bfloat162float(h));
}

// ---------------------------------------------------------------------------
// Tensor-core GEMM via baseline mma.sync (sm_80+ PTX; tcgen05 PTX is rejected
// by this toolchain's compute_103 virtual arch).
// h = x @ W with bf16 hi/lo split: xh*wh + xh*wl + xl*wh (err ~2^-16).
// Block 256 thr = 8 warps; block tile 128x128; warp tile 32x64 (m16n8k16).
// Smem k-major, row stride padded to 40 bf16 (80B) -> conflict-free LDS.32
// fragment loads for both A and B(=W^T).
// ---------------------------------------------------------------------------
#define KC 32           // k-chunk
#define APAD 40         // padded k stride in bf16 elems

__device__ __forceinline__ uint32_t pack_bf16(float a, float b) {
    __nv_bfloat162 p = __floats2bfloat162_rn(a, b);
    return *(uint32_t*)&p;
}
__device__ __forceinline__ void mma_bf16(float* d, const uint32_t* a, const uint32_t* b) {
    asm volatile(
        "mma.sync.aligned.m16n8k16.row.col.f32.bf16.bf16.f32 "
        "{%0,%1,%2,%3}, {%4,%5,%6,%7}, {%8,%9}, {%0,%1,%2,%3};"
        : "+f"(d[0]), "+f"(d[1]), "+f"(d[2]), "+f"(d[3])
        : "r"(a[0]), "r"(a[1]), "r"(a[2]), "r"(a[3]), "r"(b[0]), "r"(b[1]));
}

__global__ __launch_bounds__(256) void gemm_mma_kernel(const float* __restrict__ x) {
    __shared__ __nv_bfloat16 sAhi[128 * APAD];
    __shared__ __nv_bfloat16 sAlo[128 * APAD];
    __shared__ __nv_bfloat16 sBhi[128 * APAD];
    __shared__ __nv_bfloat16 sBlo[128 * APAD];

    const int t    = threadIdx.x;
    const int wid  = t >> 5;
    const int lane = t & 31;
    const int lr   = lane >> 2;       // fragment row/col group
    const int lc   = lane & 3;
    const int row0 = blockIdx.x * 128;
    const int mbase = (wid & 3) * 32;  // warp m offset
    const int nbase = (wid >> 2) * 64; // warp n offset

    float acc[2][8][4];
#pragma unroll
    for (int mt = 0; mt < 2; mt++)
#pragma unroll
        for (int nf = 0; nf < 8; nf++)
#pragma unroll
            for (int q = 0; q < 4; q++) acc[mt][nf][q] = 0.f;

    for (int k0 = 0; k0 < IN_F; k0 += KC) {
        // ---- stage A chunk: 128 rows x 32 k floats -> bf16 hi/lo
#pragma unroll
        for (int l = 0; l < 4; l++) {
            int idx = t + l * 256;            // 1024 float4 (128 rows x 8)
            int row = idx >> 3, q = idx & 7;
            float4 v = make_float4(0.f, 0.f, 0.f, 0.f);
            if (row0 + row < NN)
                v = *(const float4*)(x + (size_t)(row0 + row) * IN_F + k0 + q * 4);
            __nv_bfloat16 h0 = __float2bfloat16(v.x);
            __nv_bfloat16 h1 = __float2bfloat16(v.y);
            __nv_bfloat16 h2 = __float2bfloat16(v.z);
            __nv_bfloat16 h3 = __float2bfloat16(v.w);
            uint2 hp, lp;
            hp.x = pack_bf16(__bfloat162float(h0), __bfloat162float(h1));
            hp.y = pack_bf16(__bfloat162float(h2), __bfloat162float(h3));
            lp.x = pack_bf16(v.x - __bfloat162float(h0), v.y - __bfloat162float(h1));
            lp.y = pack_bf16(v.z - __bfloat162float(h2), v.w - __bfloat162float(h3));
            *(uint2*)&sAhi[row * APAD + q * 4] = hp;
            *(uint2*)&sAlo[row * APAD + q * 4] = lp;
        }
        // ---- stage B chunk: W^T [128 n][32 k] bf16; 4 uint4 (8 bf16 each) per row
#pragma unroll
        for (int l = 0; l < 2; l++) {
            int idx = t + l * 256;            // 512 uint4 (128 rows x 4)
            int n = idx >> 2, qq = idx & 3;
            *(uint4*)&sBhi[n * APAD + qq * 8] =
                *(const uint4*)(g_wt_hi + (size_t)n * IN_F + k0 + qq * 8);
            *(uint4*)&sBlo[n * APAD + qq * 8] =
                *(const uint4*)(g_wt_lo + (size_t)n * IN_F + k0 + qq * 8);
        }
        __syncthreads();

#pragma unroll
        for (int ks = 0; ks < KC; ks += 16) {
            const int kp = lc * 2 + ks;
            uint32_t ah[2][4], al[2][4], bh[8][2], bl[8][2];
#pragma unroll
            for (int mt = 0; mt < 2; mt++) {
                int R = mbase + mt * 16 + lr;
                ah[mt][0] = *(uint32_t*)&sAhi[(R)     * APAD + kp];
                ah[mt][1] = *(uint32_t*)&sAhi[(R + 8) * APAD + kp];
                ah[mt][2] = *(uint32_t*)&sAhi[(R)     * APAD + kp + 8];
                ah[mt][3] = *(uint32_t*)&sAhi[(R + 8) * APAD + kp + 8];
                al[mt][0] = *(uint32_t*)&sAlo[(R)     * APAD + kp];
                al[mt][1] = *(uint32_t*)&sAlo[(R + 8) * APAD + kp];
                al[mt][2] = *(uint32_t*)&sAlo[(R)     * APAD + kp + 8];
                al[mt][3] = *(uint32_t*)&sAlo[(R + 8) * APAD + kp + 8];
            }
#pragma unroll
            for (int nf = 0; nf < 8; nf++) {
                int Nn = nbase + nf * 8 + lr;
                bh[nf][0] = *(uint32_t*)&sBhi[Nn * APAD + kp];
                bh[nf][1] = *(uint32_t*)&sBhi[Nn * APAD + kp + 8];
                bl[nf][0] = *(uint32_t*)&sBlo[Nn * APAD + kp];
                bl[nf][1] = *(uint32_t*)&sBlo[Nn * APAD + kp + 8];
            }
#pragma unroll
            for (int mt = 0; mt < 2; mt++)
#pragma unroll
                for (int nf = 0; nf < 8; nf++) {
                    mma_bf16(acc[mt][nf], ah[mt], bh[nf]);
                    mma_bf16(acc[mt][nf], ah[mt], bl[nf]);
                    mma_bf16(acc[mt][nf], al[mt], bh[nf]);
                }
        }
        __syncthreads();
    }

    // ---- epilogue: write h (c0,c1 -> row, c2,c3 -> row+8; cols pair-contig)
#pragma unroll
    for (int mt = 0; mt < 2; mt++) {
        int r0 = row0 + mbase + mt * 16 + lr;
#pragma unroll
        for (int nf = 0; nf < 8; nf++) {
            int col = nbase + nf * 8 + lc * 2;
            if (r0 < NN)
                *(float2*)(g_h + (size_t)r0 * OUT_F + col) =
                    make_float2(acc[mt][nf][0], acc[mt][nf][1]);
            if (r0 + 8 < NN)
                *(float2*)(g_h + (size_t)(r0 + 8) * OUT_F + col) =
                    make_float2(acc[mt][nf][2], acc[mt][nf][3]);
        }
    }
}

// ---------------------------------------------------------------------------
// s_l[i] = h[i,:].a[0:128], s_r[i] = h[i,:].a[128:256]; one warp per node
// ---------------------------------------------------------------------------
__global__ void score_kernel(const float* __restrict__ a) {
    int gw   = (blockIdx.x * blockDim.x + threadIdx.x) >> 5;
    int lane = threadIdx.x & 31;
    if (gw >= NN) return;
    float4 hv = *(const float4*)(g_h + (size_t)gw * OUT_F + lane * 4);
    float4 al = *(const float4*)(a + lane * 4);
    float4 ar = *(const float4*)(a + OUT_F + lane * 4);
    float sl = hv.x * al.x + hv.y * al.y + hv.z * al.z + hv.w * al.w;
    float sr = hv.x * ar.x + hv.y * ar.y + hv.z * ar.z + hv.w * ar.w;
#pragma unroll
    for (int o = 16; o > 0; o >>= 1) {
        sl += __shfl_xor_sync(0xffffffffu, sl, o);
        sr += __shfl_xor_sync(0xffffffffu, sr, o);
    }
    if (lane == 0) { g_sl[gw] = sl; g_sr[gw] = sr; }
}

// ---------------------------------------------------------------------------
// Node-centric aggregation (no atomics, writes all of out)
// ---------------------------------------------------------------------------
__global__ __launch_bounds__(256) void agg_kernel(float* __restrict__ out) {
    int u    = (blockIdx.x * blockDim.x + threadIdx.x) >> 5;
    int lane = threadIdx.x & 31;
    if (u >= NN) return;
    int beg = g_off[u];
    int end = g_off[u + 1];
    float slu = g_sl[u];

    float4 acc = make_float4(0.f, 0.f, 0.f, 0.f);
    float  wsum = 0.f;

    for (int c = beg; c < end; c += 32) {
        int j  = c + lane;
        int dj = 0;
        float wl = 0.f;
        if (j < end) {
            dj = g_cdst[j];
            float v = slu + g_sr[dj];
            v  = (v >= 0.f) ? v : 0.2f * v;
            wl = __expf(v);
            wsum += wl;
        }
        int m = min(32, end - c);
        for (int k = 0; k < m; k++) {
            int   d = __shfl_sync(0xffffffffu, dj, k);
            float w = __shfl_sync(0xffffffffu, wl, k);
            float4 hv = *(const float4*)(g_h + (size_t)d * OUT_F + lane * 4);
            acc.x += w * hv.x;
            acc.y += w * hv.y;
            acc.z += w * hv.z;
            acc.w += w * hv.w;
        }
    }
#pragma unroll
    for (int o = 16; o > 0; o >>= 1)
        wsum += __shfl_xor_sync(0xffffffffu, wsum, o);
    float inv = 1.0f / (wsum + 1e-16f);
    float4 rr = make_float4(acc.x * inv, acc.y * inv, acc.z * inv, acc.w * inv);
    *((float4*)(out + (size_t)u * OUT_F + lane * 4)) = rr;
}

// ---------------------------------------------------------------------------
extern "C" void kernel_launch(void* const* d_in, const int* in_sizes, int n_in,
                              void* d_out, int out_size) {
    const float* x  = (const float*)d_in[0];
    const int*   ei = (const int*)d_in[1];
    const float* w  = (const float*)d_in[2];
    const float* a  = (const float*)d_in[3];
    float* out = (float*)d_out;

    // CSR build
    zero_cnt_kernel<<<(NN + 255) / 256, 256>>>();
    hist_kernel<<<(EE + 255) / 256, 256>>>(ei);
    scan_kernel<<<1, 1024>>>();
    scatter_kernel<<<(EE + 255) / 256, 256>>>(ei);

    // Dense pipeline (HMMA GEMM + scores)
    wprep_kernel<<<(OUT_F * IN_F + 255) / 256, 256>>>(w);
    gemm_mma_kernel<<<(NN + 127) / 128, 256>>>(x);
    score_kernel<<<(NN * 32 + 255) / 256, 256>>>(a);

    // Fused attention + aggregation
    agg_kernel<<<(NN * 32 + 255) / 256, 256>>>(out);
}

// round 6
// speedup vs baseline: 1.6460x; 1.0354x over previous
#include <cuda_runtime.h>
#include <cuda_bf16.h>
#include <cuda_fp16.h>
#include <math.h>
#include <cstdint>

#define NN    100000
#define EE    3200000
#define IN_F  256
#define OUT_F 128

// Scratch (allocation-free rule: __device__ globals)
__device__ __half g_hh[(size_t)NN * OUT_F];        // 25.6 MB (h in fp16, agg-only)
__device__ float g_sl[NN];
__device__ float g_sr[NN];
__device__ int   g_cnt[NN];
__device__ int   g_off[NN + 1];
__device__ int   g_fill[NN];
__device__ int   g_cdst[EE];
__device__ __nv_bfloat16 g_wt_hi[OUT_F * IN_F];    // W^T hi  [n][k]
__device__ __nv_bfloat16 g_wt_lo[OUT_F * IN_F];    // W^T lo  [n][k]

// ---------------------------------------------------------------------------
// CSR build
// ---------------------------------------------------------------------------
__global__ void zero_cnt_kernel() {
    int i = blockIdx.x * blockDim.x + threadIdx.x;
    if (i < NN) g_cnt[i] = 0;
}
__global__ void hist_kernel(const int* __restrict__ ei) {
    int e = blockIdx.x * blockDim.x + threadIdx.x;
    if (e < EE) atomicAdd(&g_cnt[ei[e]], 1);
}
__global__ __launch_bounds__(1024) void scan_kernel() {
    __shared__ int sm[1024];
    const int CHUNK = (NN + 1023) / 1024;
    int t = threadIdx.x;
    int lo = t * CHUNK, hi = min(lo + CHUNK, NN);
    int s = 0;
    for (int i = lo; i < hi; i++) s += g_cnt[i];
    sm[t] = s;
    __syncthreads();
    for (int o = 1; o < 1024; o <<= 1) {
        int v = (t >= o) ? sm[t - o] : 0;
        __syncthreads();
        sm[t] += v;
        __syncthreads();
    }
    int run = sm[t] - s;
    for (int i = lo; i < hi; i++) {
        g_off[i] = run;
        g_fill[i] = run;
        run += g_cnt[i];
    }
    if (t == 1023) g_off[NN] = sm[1023];
}
__global__ void scatter_kernel(const int* __restrict__ ei) {
    int e = blockIdx.x * blockDim.x + threadIdx.x;
    if (e >= EE) return;
    int s = ei[e], d = ei[EE + e];
    int pos = atomicAdd(&g_fill[s], 1);
    g_cdst[pos] = d;
}

// ---------------------------------------------------------------------------
// W prep: transpose + bf16 hi/lo split. Wt[n][k] = W[k][n]
// ---------------------------------------------------------------------------
__global__ void wprep_kernel(const float* __restrict__ w) {
    int i = blockIdx.x * blockDim.x + threadIdx.x;   // i = n*IN_F + k
    if (i >= OUT_F * IN_F) return;
    int n = i / IN_F, k = i % IN_F;
    float v = w[(size_t)k * OUT_F + n];
    __nv_bfloat16 h = __float2bfloat16(v);
    g_wt_hi[i] = h;
    g_wt_lo[i] = __float2bfloat16(v - __bfloat162float(h));
}

// ---------------------------------------------------------------------------
// Tensor-core GEMM (mma.sync m16n8k16 bf16, hi/lo split: xh*wh+xh*wl+xl*wh).
// Fused epilogue: writes h as fp16 (agg is the only consumer) and computes
// s_l/s_r from the exact fp32 accumulators (score kernel eliminated).
// ---------------------------------------------------------------------------
#define KC 32           // k-chunk
#define APAD 40         // padded k stride in bf16 elems

__device__ __forceinline__ uint32_t pack_bf16(float a, float b) {
    __nv_bfloat162 p = __floats2bfloat162_rn(a, b);
    return *(uint32_t*)&p;
}
__device__ __forceinline__ void mma_bf16(float* d, const uint32_t* a, const uint32_t* b) {
    asm volatile(
        "mma.sync.aligned.m16n8k16.row.col.f32.bf16.bf16.f32 "
        "{%0,%1,%2,%3}, {%4,%5,%6,%7}, {%8,%9}, {%0,%1,%2,%3};"
        : "+f"(d[0]), "+f"(d[1]), "+f"(d[2]), "+f"(d[3])
        : "r"(a[0]), "r"(a[1]), "r"(a[2]), "r"(a[3]), "r"(b[0]), "r"(b[1]));
}

__global__ __launch_bounds__(256) void gemm_mma_kernel(const float* __restrict__ x,
                                                       const float* __restrict__ a) {
    __shared__ __nv_bfloat16 sAhi[128 * APAD];
    __shared__ __nv_bfloat16 sAlo[128 * APAD];
    __shared__ __nv_bfloat16 sBhi[128 * APAD];
    __shared__ __nv_bfloat16 sBlo[128 * APAD];
    __shared__ float sS[2][128][2];   // [sl|sr][row][col-half]

    const int t    = threadIdx.x;
    const int wid  = t >> 5;
    const int lane = t & 31;
    const int lr   = lane >> 2;
    const int lc   = lane & 3;
    const int row0 = blockIdx.x * 128;
    const int mbase = (wid & 3) * 32;
    const int nbase = (wid >> 2) * 64;
    const int hw    = wid >> 2;        // column half owned by this warp

    float acc[2][8][4];
#pragma unroll
    for (int mt = 0; mt < 2; mt++)
#pragma unroll
        for (int nf = 0; nf < 8; nf++)
#pragma unroll
            for (int q = 0; q < 4; q++) acc[mt][nf][q] = 0.f;

    for (int k0 = 0; k0 < IN_F; k0 += KC) {
        // ---- stage A chunk: 128 rows x 32 k floats -> bf16 hi/lo
#pragma unroll
        for (int l = 0; l < 4; l++) {
            int idx = t + l * 256;            // 1024 float4 (128 rows x 8)
            int row = idx >> 3, q = idx & 7;
            float4 v = make_float4(0.f, 0.f, 0.f, 0.f);
            if (row0 + row < NN)
                v = *(const float4*)(x + (size_t)(row0 + row) * IN_F + k0 + q * 4);
            __nv_bfloat16 h0 = __float2bfloat16(v.x);
            __nv_bfloat16 h1 = __float2bfloat16(v.y);
            __nv_bfloat16 h2 = __float2bfloat16(v.z);
            __nv_bfloat16 h3 = __float2bfloat16(v.w);
            uint2 hp, lp;
            hp.x = pack_bf16(__bfloat162float(h0), __bfloat162float(h1));
            hp.y = pack_bf16(__bfloat162float(h2), __bfloat162float(h3));
            lp.x = pack_bf16(v.x - __bfloat162float(h0), v.y - __bfloat162float(h1));
            lp.y = pack_bf16(v.z - __bfloat162float(h2), v.w - __bfloat162float(h3));
            *(uint2*)&sAhi[row * APAD + q * 4] = hp;
            *(uint2*)&sAlo[row * APAD + q * 4] = lp;
        }
        // ---- stage B chunk: W^T [128 n][32 k] bf16; 4 uint4 (8 bf16) per row
#pragma unroll
        for (int l = 0; l < 2; l++) {
            int idx = t + l * 256;            // 512 uint4 (128 rows x 4)
            int n = idx >> 2, qq = idx & 3;
            *(uint4*)&sBhi[n * APAD + qq * 8] =
                *(const uint4*)(g_wt_hi + (size_t)n * IN_F + k0 + qq * 8);
            *(uint4*)&sBlo[n * APAD + qq * 8] =
                *(const uint4*)(g_wt_lo + (size_t)n * IN_F + k0 + qq * 8);
        }
        __syncthreads();

#pragma unroll
        for (int ks = 0; ks < KC; ks += 16) {
            const int kp = lc * 2 + ks;
            uint32_t ah[2][4], al[2][4], bh[8][2], bl[8][2];
#pragma unroll
            for (int mt = 0; mt < 2; mt++) {
                int R = mbase + mt * 16 + lr;
                ah[mt][0] = *(uint32_t*)&sAhi[(R)     * APAD + kp];
                ah[mt][1] = *(uint32_t*)&sAhi[(R + 8) * APAD + kp];
                ah[mt][2] = *(uint32_t*)&sAhi[(R)     * APAD + kp + 8];
                ah[mt][3] = *(uint32_t*)&sAhi[(R + 8) * APAD + kp + 8];
                al[mt][0] = *(uint32_t*)&sAlo[(R)     * APAD + kp];
                al[mt][1] = *(uint32_t*)&sAlo[(R + 8) * APAD + kp];
                al[mt][2] = *(uint32_t*)&sAlo[(R)     * APAD + kp + 8];
                al[mt][3] = *(uint32_t*)&sAlo[(R + 8) * APAD + kp + 8];
            }
#pragma unroll
            for (int nf = 0; nf < 8; nf++) {
                int Nn = nbase + nf * 8 + lr;
                bh[nf][0] = *(uint32_t*)&sBhi[Nn * APAD + kp];
                bh[nf][1] = *(uint32_t*)&sBhi[Nn * APAD + kp + 8];
                bl[nf][0] = *(uint32_t*)&sBlo[Nn * APAD + kp];
                bl[nf][1] = *(uint32_t*)&sBlo[Nn * APAD + kp + 8];
            }
#pragma unroll
            for (int mt = 0; mt < 2; mt++)
#pragma unroll
                for (int nf = 0; nf < 8; nf++) {
                    mma_bf16(acc[mt][nf], ah[mt], bh[nf]);
                    mma_bf16(acc[mt][nf], ah[mt], bl[nf]);
                    mma_bf16(acc[mt][nf], al[mt], bh[nf]);
                }
        }
        __syncthreads();
    }

    // ---- epilogue: fp16 h store + fused s_l/s_r
    float psl[2][2] = {{0.f, 0.f}, {0.f, 0.f}};   // [mt][row/row+8]
    float psr[2][2] = {{0.f, 0.f}, {0.f, 0.f}};
#pragma unroll
    for (int mt = 0; mt < 2; mt++) {
        int r0 = row0 + mbase + mt * 16 + lr;
#pragma unroll
        for (int nf = 0; nf < 8; nf++) {
            int col = nbase + nf * 8 + lc * 2;
            float a0 = __ldg(a + col), a1 = __ldg(a + col + 1);
            float b0 = __ldg(a + OUT_F + col), b1 = __ldg(a + OUT_F + col + 1);
            psl[mt][0] += acc[mt][nf][0] * a0 + acc[mt][nf][1] * a1;
            psr[mt][0] += acc[mt][nf][0] * b0 + acc[mt][nf][1] * b1;
            psl[mt][1] += acc[mt][nf][2] * a0 + acc[mt][nf][3] * a1;
            psr[mt][1] += acc[mt][nf][2] * b0 + acc[mt][nf][3] * b1;
            if (r0 < NN)
                *(__half2*)(g_hh + (size_t)r0 * OUT_F + col) =
                    __floats2half2_rn(acc[mt][nf][0], acc[mt][nf][1]);
            if (r0 + 8 < NN)
                *(__half2*)(g_hh + (size_t)(r0 + 8) * OUT_F + col) =
                    __floats2half2_rn(acc[mt][nf][2], acc[mt][nf][3]);
        }
    }
    // quad reduce over lc (lanes lr*4 + 0..3)
#pragma unroll
    for (int o = 1; o <= 2; o <<= 1)
#pragma unroll
        for (int mt = 0; mt < 2; mt++)
#pragma unroll
            for (int i = 0; i < 2; i++) {
                psl[mt][i] += __shfl_xor_sync(0xffffffffu, psl[mt][i], o);
                psr[mt][i] += __shfl_xor_sync(0xffffffffu, psr[mt][i], o);
            }
    if (lc == 0) {
#pragma unroll
        for (int mt = 0; mt < 2; mt++)
#pragma unroll
            for (int i = 0; i < 2; i++) {
                int rl = mbase + mt * 16 + lr + i * 8;
                sS[0][rl][hw] = psl[mt][i];
                sS[1][rl][hw] = psr[mt][i];
            }
    }
    __syncthreads();
    if (t < 128) {
        int row = row0 + t;
        if (row < NN) {
            g_sl[row] = sS[0][t][0] + sS[0][t][1];
            g_sr[row] = sS[1][t][0] + sS[1][t][1];
        }
    }
}

// ---------------------------------------------------------------------------
// Node-centric aggregation: fp16 h gather (256B/edge), fp32 accumulate.
// ---------------------------------------------------------------------------
__global__ __launch_bounds__(256) void agg_kernel(float* __restrict__ out) {
    int u    = (blockIdx.x * blockDim.x + threadIdx.x) >> 5;
    int lane = threadIdx.x & 31;
    if (u >= NN) return;
    int beg = g_off[u];
    int end = g_off[u + 1];
    float slu = g_sl[u];

    float4 acc = make_float4(0.f, 0.f, 0.f, 0.f);
    float  wsum = 0.f;

    for (int c = beg; c < end; c += 32) {
        int j  = c + lane;
        int dj = 0;
        float wl = 0.f;
        if (j < end) {
            dj = g_cdst[j];
            float v = slu + g_sr[dj];
            v  = (v >= 0.f) ? v : 0.2f * v;
            wl = __expf(v);
            wsum += wl;
        }
        int m = min(32, end - c);
        for (int k = 0; k < m; k++) {
            int   d = __shfl_sync(0xffffffffu, dj, k);
            float w = __shfl_sync(0xffffffffu, wl, k);
            const __half2* hp = (const __half2*)(g_hh + (size_t)d * OUT_F + lane * 4);
            float2 f0 = __half22float2(hp[0]);
            float2 f1 = __half22float2(hp[1]);
            acc.x += w * f0.x;
            acc.y += w * f0.y;
            acc.z += w * f1.x;
            acc.w += w * f1.y;
        }
    }
#pragma unroll
    for (int o = 16; o > 0; o >>= 1)
        wsum += __shfl_xor_sync(0xffffffffu, wsum, o);
    float inv = 1.0f / (wsum + 1e-16f);
    float4 rr = make_float4(acc.x * inv, acc.y * inv, acc.z * inv, acc.w * inv);
    *((float4*)(out + (size_t)u * OUT_F + lane * 4)) = rr;
}

// ---------------------------------------------------------------------------
extern "C" void kernel_launch(void* const* d_in, const int* in_sizes, int n_in,
                              void* d_out, int out_size) {
    const float* x  = (const float*)d_in[0];
    const int*   ei = (const int*)d_in[1];
    const float* w  = (const float*)d_in[2];
    const float* a  = (const float*)d_in[3];
    float* out = (float*)d_out;

    // CSR build
    zero_cnt_kernel<<<(NN + 255) / 256, 256>>>();
    hist_kernel<<<(EE + 255) / 256, 256>>>(ei);
    scan_kernel<<<1, 1024>>>();
    scatter_kernel<<<(EE + 255) / 256, 256>>>(ei);

    // Dense pipeline (HMMA GEMM + fused scores + fp16 h)
    wprep_kernel<<<(OUT_F * IN_F + 255) / 256, 256>>>(w);
    gemm_mma_kernel<<<(NN + 127) / 128, 256>>>(x, a);

    // Fused attention + aggregation
    agg_kernel<<<(NN * 32 + 255) / 256, 256>>>(out);
}

// round 7
// speedup vs baseline: 1.6847x; 1.0235x over previous
#include <cuda_runtime.h>
#include <cuda_bf16.h>
#include <cuda_fp16.h>
#include <math.h>
#include <cstdint>

#define NN    100000
#define EE    3200000
#define IN_F  256
#define OUT_F 128

// Scratch (allocation-free rule: __device__ globals)
__device__ __half g_hh[(size_t)NN * OUT_F];        // 25.6 MB (h in fp16, agg-only)
__device__ float g_sl[NN];
__device__ float g_sr[NN];
__device__ int   g_cnt[NN];
__device__ int   g_off[NN + 1];
__device__ int   g_fill[NN];
__device__ int   g_cdst[EE];
__device__ __nv_bfloat16 g_wt_hi[OUT_F * IN_F];    // W^T hi  [n][k]
__device__ __nv_bfloat16 g_wt_lo[OUT_F * IN_F];    // W^T lo  [n][k]

// ---------------------------------------------------------------------------
// CSR build (4 edges per thread -> 4 independent atomic chains = MLP 4)
// ---------------------------------------------------------------------------
__global__ void zero_cnt_kernel() {
    int i = blockIdx.x * blockDim.x + threadIdx.x;
    if (i < NN) g_cnt[i] = 0;
}
__global__ void hist_kernel(const int* __restrict__ ei) {
    int base = blockIdx.x * 1024 + threadIdx.x;
#pragma unroll
    for (int l = 0; l < 4; l++) {
        int e = base + l * 256;
        if (e < EE) atomicAdd(&g_cnt[ei[e]], 1);
    }
}
__global__ __launch_bounds__(1024) void scan_kernel() {
    __shared__ int sm[1024];
    const int CHUNK = (NN + 1023) / 1024;
    int t = threadIdx.x;
    int lo = t * CHUNK, hi = min(lo + CHUNK, NN);
    int s = 0;
    for (int i = lo; i < hi; i++) s += g_cnt[i];
    sm[t] = s;
    __syncthreads();
    for (int o = 1; o < 1024; o <<= 1) {
        int v = (t >= o) ? sm[t - o] : 0;
        __syncthreads();
        sm[t] += v;
        __syncthreads();
    }
    int run = sm[t] - s;
    for (int i = lo; i < hi; i++) {
        g_off[i] = run;
        g_fill[i] = run;
        run += g_cnt[i];
    }
    if (t == 1023) g_off[NN] = sm[1023];
}
__global__ void scatter_kernel(const int* __restrict__ ei) {
    int base = blockIdx.x * 1024 + threadIdx.x;
    int sidx[4], didx[4];
#pragma unroll
    for (int l = 0; l < 4; l++) {
        int e = base + l * 256;
        sidx[l] = (e < EE) ? ei[e] : -1;
        didx[l] = (e < EE) ? ei[EE + e] : 0;
    }
#pragma unroll
    for (int l = 0; l < 4; l++) {
        if (sidx[l] >= 0) {
            int pos = atomicAdd(&g_fill[sidx[l]], 1);
            g_cdst[pos] = didx[l];
        }
    }
}

// ---------------------------------------------------------------------------
// W prep: transpose + bf16 hi/lo split. Wt[n][k] = W[k][n]
// ---------------------------------------------------------------------------
__global__ void wprep_kernel(const float* __restrict__ w) {
    int i = blockIdx.x * blockDim.x + threadIdx.x;   // i = n*IN_F + k
    if (i >= OUT_F * IN_F) return;
    int n = i / IN_F, k = i % IN_F;
    float v = w[(size_t)k * OUT_F + n];
    __nv_bfloat16 h = __float2bfloat16(v);
    g_wt_hi[i] = h;
    g_wt_lo[i] = __float2bfloat16(v - __bfloat162float(h));
}

// ---------------------------------------------------------------------------
// Tensor-core GEMM (mma.sync m16n8k16 bf16, hi/lo split) with A-prefetch
// pipelining. Fused epilogue: fp16 h store + s_l/s_r from fp32 accumulators.
// ---------------------------------------------------------------------------
#define KC 32           // k-chunk
#define APAD 40         // padded k stride in bf16 elems

__device__ __forceinline__ uint32_t pack_bf16(float a, float b) {
    __nv_bfloat162 p = __floats2bfloat162_rn(a, b);
    return *(uint32_t*)&p;
}
__device__ __forceinline__ void mma_bf16(float* d, const uint32_t* a, const uint32_t* b) {
    asm volatile(
        "mma.sync.aligned.m16n8k16.row.col.f32.bf16.bf16.f32 "
        "{%0,%1,%2,%3}, {%4,%5,%6,%7}, {%8,%9}, {%0,%1,%2,%3};"
        : "+f"(d[0]), "+f"(d[1]), "+f"(d[2]), "+f"(d[3])
        : "r"(a[0]), "r"(a[1]), "r"(a[2]), "r"(a[3]), "r"(b[0]), "r"(b[1]));
}

__global__ __launch_bounds__(256) void gemm_mma_kernel(const float* __restrict__ x,
                                                       const float* __restrict__ a) {
    __shared__ __nv_bfloat16 sAhi[128 * APAD];
    __shared__ __nv_bfloat16 sAlo[128 * APAD];
    __shared__ __nv_bfloat16 sBhi[128 * APAD];
    __shared__ __nv_bfloat16 sBlo[128 * APAD];
    __shared__ float sS[2][128][2];   // [sl|sr][row][col-half]

    const int t    = threadIdx.x;
    const int wid  = t >> 5;
    const int lane = t & 31;
    const int lr   = lane >> 2;
    const int lc   = lane & 3;
    const int row0 = blockIdx.x * 128;
    const int mbase = (wid & 3) * 32;
    const int nbase = (wid >> 2) * 64;
    const int hw    = wid >> 2;

    float acc[2][8][4];
#pragma unroll
    for (int mt = 0; mt < 2; mt++)
#pragma unroll
        for (int nf = 0; nf < 8; nf++)
#pragma unroll
            for (int q = 0; q < 4; q++) acc[mt][nf][q] = 0.f;

    // A staging geometry: 1024 float4 per chunk; this thread covers idx = t + l*256
    float4 va[4];
#pragma unroll
    for (int l = 0; l < 4; l++) {
        int idx = t + l * 256;
        int row = idx >> 3, q = idx & 7;
        va[l] = make_float4(0.f, 0.f, 0.f, 0.f);
        if (row0 + row < NN)
            va[l] = *(const float4*)(x + (size_t)(row0 + row) * IN_F + 0 + q * 4);
    }

    for (int c = 0; c < IN_F / KC; c++) {
        int k0 = c * KC;
        // ---- convert prefetched A regs -> smem hi/lo
#pragma unroll
        for (int l = 0; l < 4; l++) {
            int idx = t + l * 256;
            int row = idx >> 3, q = idx & 7;
            float4 v = va[l];
            __nv_bfloat16 h0 = __float2bfloat16(v.x);
            __nv_bfloat16 h1 = __float2bfloat16(v.y);
            __nv_bfloat16 h2 = __float2bfloat16(v.z);
            __nv_bfloat16 h3 = __float2bfloat16(v.w);
            uint2 hp, lp;
            hp.x = pack_bf16(__bfloat162float(h0), __bfloat162float(h1));
            hp.y = pack_bf16(__bfloat162float(h2), __bfloat162float(h3));
            lp.x = pack_bf16(v.x - __bfloat162float(h0), v.y - __bfloat162float(h1));
            lp.y = pack_bf16(v.z - __bfloat162float(h2), v.w - __bfloat162float(h3));
            *(uint2*)&sAhi[row * APAD + q * 4] = hp;
            *(uint2*)&sAlo[row * APAD + q * 4] = lp;
        }
        // ---- stage B chunk: W^T [128 n][32 k] bf16; 4 uint4 (8 bf16) per row
#pragma unroll
        for (int l = 0; l < 2; l++) {
            int idx = t + l * 256;
            int n = idx >> 2, qq = idx & 3;
            *(uint4*)&sBhi[n * APAD + qq * 8] =
                *(const uint4*)(g_wt_hi + (size_t)n * IN_F + k0 + qq * 8);
            *(uint4*)&sBlo[n * APAD + qq * 8] =
                *(const uint4*)(g_wt_lo + (size_t)n * IN_F + k0 + qq * 8);
        }
        __syncthreads();

        // ---- prefetch next A chunk (LDGs land during the MMA block)
        if (c + 1 < IN_F / KC) {
#pragma unroll
            for (int l = 0; l < 4; l++) {
                int idx = t + l * 256;
                int row = idx >> 3, q = idx & 7;
                if (row0 + row < NN)
                    va[l] = *(const float4*)(x + (size_t)(row0 + row) * IN_F +
                                             (k0 + KC) + q * 4);
                else
                    va[l] = make_float4(0.f, 0.f, 0.f, 0.f);
            }
        }

#pragma unroll
        for (int ks = 0; ks < KC; ks += 16) {
            const int kp = lc * 2 + ks;
            uint32_t ah[2][4], al[2][4], bh[8][2], bl[8][2];
#pragma unroll
            for (int mt = 0; mt < 2; mt++) {
                int R = mbase + mt * 16 + lr;
                ah[mt][0] = *(uint32_t*)&sAhi[(R)     * APAD + kp];
                ah[mt][1] = *(uint32_t*)&sAhi[(R + 8) * APAD + kp];
                ah[mt][2] = *(uint32_t*)&sAhi[(R)     * APAD + kp + 8];
                ah[mt][3] = *(uint32_t*)&sAhi[(R + 8) * APAD + kp + 8];
                al[mt][0] = *(uint32_t*)&sAlo[(R)     * APAD + kp];
                al[mt][1] = *(uint32_t*)&sAlo[(R + 8) * APAD + kp];
                al[mt][2] = *(uint32_t*)&sAlo[(R)     * APAD + kp + 8];
                al[mt][3] = *(uint32_t*)&sAlo[(R + 8) * APAD + kp + 8];
            }
#pragma unroll
            for (int nf = 0; nf < 8; nf++) {
                int Nn = nbase + nf * 8 + lr;
                bh[nf][0] = *(uint32_t*)&sBhi[Nn * APAD + kp];
                bh[nf][1] = *(uint32_t*)&sBhi[Nn * APAD + kp + 8];
                bl[nf][0] = *(uint32_t*)&sBlo[Nn * APAD + kp];
                bl[nf][1] = *(uint32_t*)&sBlo[Nn * APAD + kp + 8];
            }
#pragma unroll
            for (int mt = 0; mt < 2; mt++)
#pragma unroll
                for (int nf = 0; nf < 8; nf++) {
                    mma_bf16(acc[mt][nf], ah[mt], bh[nf]);
                    mma_bf16(acc[mt][nf], ah[mt], bl[nf]);
                    mma_bf16(acc[mt][nf], al[mt], bh[nf]);
                }
        }
        __syncthreads();
    }

    // ---- epilogue: fp16 h store + fused s_l/s_r
    float psl[2][2] = {{0.f, 0.f}, {0.f, 0.f}};
    float psr[2][2] = {{0.f, 0.f}, {0.f, 0.f}};
#pragma unroll
    for (int mt = 0; mt < 2; mt++) {
        int r0 = row0 + mbase + mt * 16 + lr;
#pragma unroll
        for (int nf = 0; nf < 8; nf++) {
            int col = nbase + nf * 8 + lc * 2;
            float a0 = __ldg(a + col), a1 = __ldg(a + col + 1);
            float b0 = __ldg(a + OUT_F + col), b1 = __ldg(a + OUT_F + col + 1);
            psl[mt][0] += acc[mt][nf][0] * a0 + acc[mt][nf][1] * a1;
            psr[mt][0] += acc[mt][nf][0] * b0 + acc[mt][nf][1] * b1;
            psl[mt][1] += acc[mt][nf][2] * a0 + acc[mt][nf][3] * a1;
            psr[mt][1] += acc[mt][nf][2] * b0 + acc[mt][nf][3] * b1;
            if (r0 < NN)
                *(__half2*)(g_hh + (size_t)r0 * OUT_F + col) =
                    __floats2half2_rn(acc[mt][nf][0], acc[mt][nf][1]);
            if (r0 + 8 < NN)
                *(__half2*)(g_hh + (size_t)(r0 + 8) * OUT_F + col) =
                    __floats2half2_rn(acc[mt][nf][2], acc[mt][nf][3]);
        }
    }
#pragma unroll
    for (int o = 1; o <= 2; o <<= 1)
#pragma unroll
        for (int mt = 0; mt < 2; mt++)
#pragma unroll
            for (int i = 0; i < 2; i++) {
                psl[mt][i] += __shfl_xor_sync(0xffffffffu, psl[mt][i], o);
                psr[mt][i] += __shfl_xor_sync(0xffffffffu, psr[mt][i], o);
            }
    if (lc == 0) {
#pragma unroll
        for (int mt = 0; mt < 2; mt++)
#pragma unroll
            for (int i = 0; i < 2; i++) {
                int rl = mbase + mt * 16 + lr + i * 8;
                sS[0][rl][hw] = psl[mt][i];
                sS[1][rl][hw] = psr[mt][i];
            }
    }
    __syncthreads();
    if (t < 128) {
        int row = row0 + t;
        if (row < NN) {
            g_sl[row] = sS[0][t][0] + sS[0][t][1];
            g_sr[row] = sS[1][t][0] + sS[1][t][1];
        }
    }
}

// ---------------------------------------------------------------------------
// Node-centric aggregation: 4-edge interleaved gather (MLP 4).
// ---------------------------------------------------------------------------
__global__ __launch_bounds__(256) void agg_kernel(float* __restrict__ out) {
    int u    = (blockIdx.x * blockDim.x + threadIdx.x) >> 5;
    int lane = threadIdx.x & 31;
    if (u >= NN) return;
    int beg = g_off[u];
    int end = g_off[u + 1];
    float slu = g_sl[u];

    float4 acc = make_float4(0.f, 0.f, 0.f, 0.f);
    float  wsum = 0.f;

    for (int c = beg; c < end; c += 32) {
        int j  = c + lane;
        int dj = 0;
        float wl = 0.f;
        if (j < end) {
            dj = g_cdst[j];
            float v = slu + g_sr[dj];
            v  = (v >= 0.f) ? v : 0.2f * v;
            wl = __expf(v);
            wsum += wl;
        }
        int m = min(32, end - c);
        int k = 0;
        for (; k + 4 <= m; k += 4) {
            int d0 = __shfl_sync(0xffffffffu, dj, k);
            int d1 = __shfl_sync(0xffffffffu, dj, k + 1);
            int d2 = __shfl_sync(0xffffffffu, dj, k + 2);
            int d3 = __shfl_sync(0xffffffffu, dj, k + 3);
            float w0 = __shfl_sync(0xffffffffu, wl, k);
            float w1 = __shfl_sync(0xffffffffu, wl, k + 1);
            float w2 = __shfl_sync(0xffffffffu, wl, k + 2);
            float w3 = __shfl_sync(0xffffffffu, wl, k + 3);
            // 4 independent 8B gathers in flight
            uint2 r0 = *(const uint2*)(g_hh + (size_t)d0 * OUT_F + lane * 4);
            uint2 r1 = *(const uint2*)(g_hh + (size_t)d1 * OUT_F + lane * 4);
            uint2 r2 = *(const uint2*)(g_hh + (size_t)d2 * OUT_F + lane * 4);
            uint2 r3 = *(const uint2*)(g_hh + (size_t)d3 * OUT_F + lane * 4);
            float2 p, q;
            p = __half22float2(*(__half2*)&r0.x); q = __half22float2(*(__half2*)&r0.y);
            acc.x += w0 * p.x; acc.y += w0 * p.y; acc.z += w0 * q.x; acc.w += w0 * q.y;
            p = __half22float2(*(__half2*)&r1.x); q = __half22float2(*(__half2*)&r1.y);
            acc.x += w1 * p.x; acc.y += w1 * p.y; acc.z += w1 * q.x; acc.w += w1 * q.y;
            p = __half22float2(*(__half2*)&r2.x); q = __half22float2(*(__half2*)&r2.y);
            acc.x += w2 * p.x; acc.y += w2 * p.y; acc.z += w2 * q.x; acc.w += w2 * q.y;
            p = __half22float2(*(__half2*)&r3.x); q = __half22float2(*(__half2*)&r3.y);
            acc.x += w3 * p.x; acc.y += w3 * p.y; acc.z += w3 * q.x; acc.w += w3 * q.y;
        }
        for (; k < m; k++) {
            int   d = __shfl_sync(0xffffffffu, dj, k);
            float w = __shfl_sync(0xffffffffu, wl, k);
            uint2 r0 = *(const uint2*)(g_hh + (size_t)d * OUT_F + lane * 4);
            float2 p = __half22float2(*(__half2*)&r0.x);
            float2 q = __half22float2(*(__half2*)&r0.y);
            acc.x += w * p.x; acc.y += w * p.y; acc.z += w * q.x; acc.w += w * q.y;
        }
    }
#pragma unroll
    for (int o = 16; o > 0; o >>= 1)
        wsum += __shfl_xor_sync(0xffffffffu, wsum, o);
    float inv = 1.0f / (wsum + 1e-16f);
    float4 rr = make_float4(acc.x * inv, acc.y * inv, acc.z * inv, acc.w * inv);
    *((float4*)(out + (size_t)u * OUT_F + lane * 4)) = rr;
}

// ---------------------------------------------------------------------------
extern "C" void kernel_launch(void* const* d_in, const int* in_sizes, int n_in,
                              void* d_out, int out_size) {
    const float* x  = (const float*)d_in[0];
    const int*   ei = (const int*)d_in[1];
    const float* w  = (const float*)d_in[2];
    const float* a  = (const float*)d_in[3];
    float* out = (float*)d_out;

    // CSR build
    zero_cnt_kernel<<<(NN + 255) / 256, 256>>>();
    hist_kernel<<<(EE + 1023) / 1024, 256>>>(ei);
    scan_kernel<<<1, 1024>>>();
    scatter_kernel<<<(EE + 1023) / 1024, 256>>>(ei);

    // Dense pipeline (HMMA GEMM + fused scores + fp16 h)
    wprep_kernel<<<(OUT_F * IN_F + 255) / 256, 256>>>(w);
    gemm_mma_kernel<<<(NN + 127) / 128, 256>>>(x, a);

    // Fused attention + aggregation
    agg_kernel<<<(NN * 32 + 255) / 256, 256>>>(out);
}